// round 5
// baseline (speedup 1.0000x reference)
#include <cuda_runtime.h>
#include <cuda_bf16.h>
#include <cstdint>
#include <cstddef>

#define NB   1024
#define NM   14
#define NBLK 148
#define WPB  7                 // warps (=buckets) per block
#define NTHR (WPB * 32)        // 224

// Inflow ping-pong buffers + barrier state. Self-resetting:
//  - inflow: zeroed at kernel start (own slice per warp), consumer-zeroed per layer
//  - g_ctr/g_exit: reset by the last-exiting block at kernel end
__device__ float    g_inflow[2][NB];
__device__ unsigned g_ctr;
__device__ unsigned g_exit;

__device__ __forceinline__ float sqrt_approx(float x) {
    float y; asm("sqrt.approx.f32 %0, %1;" : "=f"(y) : "f"(x)); return y;
}
__device__ __forceinline__ void cp16(uint32_t saddr, const void* g) {
    asm volatile("cp.async.cg.shared.global [%0], [%1], 16;" :: "r"(saddr), "l"(g));
}
__device__ __forceinline__ void cp_commit() { asm volatile("cp.async.commit_group;"); }
__device__ __forceinline__ void cp_wait0()  { asm volatile("cp.async.wait_group 0;" ::: "memory"); }
__device__ __forceinline__ unsigned ld_acq(const unsigned* p) {
    unsigned v; asm volatile("ld.acquire.gpu.global.u32 %0, [%1];" : "=r"(v) : "l"(p)); return v;
}

// Grid-wide barrier: all threads of all blocks call. Monotonic counter, one
// increment per block per phase; release via acquire-poll. Cumulative fence
// semantics: __syncthreads -> thread0 fence+red makes the whole block's prior
// writes visible to any thread that acquires the counter.
__device__ __forceinline__ void grid_barrier(unsigned target) {
    __syncthreads();
    if (threadIdx.x == 0) {
        __threadfence();
        atomicAdd(&g_ctr, 1u);
        while (ld_acq(&g_ctr) < target) { }
    }
    __syncthreads();
}

// Stage one bucket row (8KB S + 4KB theta) into smem via cp.async (warp-wide).
__device__ __forceinline__ void stage_bucket_cp(char* dst, const float* Sbase,
                                                const float* Tbase, size_t row, int lane)
{
    const char* gs = (const char*)Sbase + row * 8192;
    const char* gt = (const char*)Tbase + row * 4096;
    uint32_t ss = (uint32_t)__cvta_generic_to_shared(dst);
    #pragma unroll
    for (int k = 0; k < 16; ++k)
        cp16(ss + (uint32_t)(lane + k * 32) * 16, gs + (size_t)(lane + k * 32) * 16);
    uint32_t st = ss + 8192;
    #pragma unroll
    for (int k = 0; k < 8; ++k)
        cp16(st + (uint32_t)(lane + k * 32) * 16, gt + (size_t)(lane + k * 32) * 16);
}

// Exact sequential bucket recurrence from smem, warp-cooperative.
// Dry spigots leave H_eff bit-identical -> only firing spigots (lowest index
// first via ballot) are serialized. Window w drains fully before w+1 (index
// order preserved). Firing q flushed per window (predicated, off chain path).
template <bool ATOMIC>
__device__ float chain_smem(const char* bucket, int lane, float H0, float inflow,
                            float* __restrict__ nxt)
{
    const unsigned FULL = 0xFFFFFFFFu;
    const float SQ2G = 4.4271887242357310f;    // sqrt(2*9.8)
    const float2* __restrict__ S2 = (const float2*)bucket;
    const float*  __restrict__ T  = (const float*)(bucket + 8192);

    // spigot 0: H_eff = H0 + inflow (reference quirk); broadcast smem reads
    float2 s0 = S2[0];
    float  t0 = T[0];
    float  h0 = fmaxf((H0 + inflow) - s0.x, 0.0f);
    float  q0 = t0 * s0.y * SQ2G * sqrt_approx(h0);
    float  cum = q0;
    float  H_eff = fmaf(-0.5f, cum, H0);

    // 1-deep smem prefetch of the next 32-spigot window
    float2 pn = S2[lane];
    float  tn = T[lane];

    for (int w = 0; w < 32; ++w) {
        float2 p = pn; float th = tn;
        if (w < 31) { pn = S2[(w + 1) * 32 + lane]; tn = T[(w + 1) * 32 + lane]; }
        float bh = p.x;
        float cc = p.y * th * SQ2G;
        float qacc = (w == 0 && lane == 0) ? q0 : 0.0f;
        unsigned rem = (w == 0) ? 0xFFFFFFFEu : FULL;   // spigot 0 already done
        while (true) {
            float h = H_eff - bh;
            unsigned fire = __ballot_sync(FULL, h > 0.0f) & rem;
            if (!fire) break;
            float q = cc * sqrt_approx(h);              // speculative, off path
            int f = __ffs(fire) - 1;                    // lowest firing spigot
            float qf = __shfl_sync(FULL, q, f);
            cum += qf;
            H_eff = fmaf(-0.5f, cum, H0);
            qacc = (lane == f) ? qf : qacc;
            rem &= (0xFFFFFFFEu << f);
        }
        if (qacc != 0.0f) {
            if (ATOMIC) atomicAdd(&nxt[w * 32 + lane], qacc);
            else        nxt[w * 32 + lane] = qacc;
        }
    }
    return cum;
}

// ---------------------------------------------------------------------------
// Single persistent kernel: 148 blocks x 224 threads, 1 block/SM (180KB smem).
// smem: buf0[7x12KB] | buf1[7x12KB] | head[12KB]
// ---------------------------------------------------------------------------
__global__ void __launch_bounds__(NTHR, 1)
k_cascade(const float* __restrict__ H0p,   const float* __restrict__ H_mid,
          const float* __restrict__ H_last,const float* __restrict__ S0,
          const float* __restrict__ S_mid, const float* __restrict__ S_last,
          const float* __restrict__ theta0,const float* __restrict__ theta_mid,
          const float* __restrict__ theta_last, const float* __restrict__ precip,
          float* __restrict__ out)
{
    extern __shared__ char smem[];
    const int tid  = threadIdx.x;
    const int lane = tid & 31;
    const int w    = tid >> 5;                 // 0..6
    const int b    = blockIdx.x * WPB + w;     // bucket id (may be >= NB)

    char* buf[2] = { smem, smem + WPB * 12288 };
    char* headb  = smem + 2 * WPB * 12288;

    const float pre      = precip[0];
    const float p_layer  = pre * (1.0f / 16.0f);
    const float p_bucket = p_layer * (1.0f / 1024.0f);

    // zero inflow slices (both buffers) for this replay
    if (lane == 0 && b < NB) { g_inflow[0][b] = 0.0f; g_inflow[1][b] = 0.0f; }

    // stage mid layer 0 + head bucket data
    if (b < NB) stage_bucket_cp(buf[0] + w * 12288, S_mid, theta_mid, (size_t)b, lane);
    if (blockIdx.x == 0 && w == 0) {
        uint32_t ss = (uint32_t)__cvta_generic_to_shared(headb);
        #pragma unroll
        for (int k = 0; k < 16; ++k)
            cp16(ss + (uint32_t)(lane + k * 32) * 16, (const char*)S0 + (size_t)(lane + k * 32) * 16);
        #pragma unroll
        for (int k = 0; k < 8; ++k)
            cp16(ss + 8192 + (uint32_t)(lane + k * 32) * 16, (const char*)theta0 + (size_t)(lane + k * 32) * 16);
    }
    cp_commit();

    unsigned phase = 1;
    grid_barrier(NBLK * phase); ++phase;       // zeros visible grid-wide

    // head bucket chain (block 0, warp 0); q0 -> g_inflow[0] (plain stores)
    if (blockIdx.x == 0 && w == 0) {
        cp_wait0();
        __syncwarp();
        float H0 = H0p[0];
        float cum = chain_smem<false>(headb, lane, H0, p_layer, g_inflow[0]);
        if (lane == 0) out[0] = (H0 - cum) + p_layer;
    }
    grid_barrier(NBLK * phase); ++phase;       // q0 visible

    // mid layers: chain layer l from buf[l&1] while staging l+1 into buf[(l&1)^1]
    for (int l = 0; l < NM; ++l) {
        const int cur = l & 1;
        cp_wait0();                            // layer-l smem data complete
        __syncthreads();                       // cross-lane smem visibility
        if (l + 1 < NM && b < NB)
            stage_bucket_cp(buf[cur ^ 1] + w * 12288, S_mid, theta_mid,
                            (size_t)(l + 1) * NB + (size_t)b, lane);
        cp_commit();

        if (b < NB) {
            float inf0 = 0.0f;
            if (lane == 0) { inf0 = g_inflow[cur][b]; g_inflow[cur][b] = 0.0f; }
            float inflow = __shfl_sync(0xFFFFFFFFu, inf0, 0) + p_bucket;
            float H0 = H_mid[(size_t)l * NB + b];
            float cum = chain_smem<true>(buf[cur] + w * 12288, lane, H0, inflow,
                                         g_inflow[cur ^ 1]);
            if (lane == 0) out[1 + l * NB + b] = (H0 - cum) + inflow;
        }
        grid_barrier(NBLK * phase); ++phase;   // layer-l atomics visible
    }

    // last layer: single outlet spigot per bucket (inflows in g_inflow[0])
    if (b < NB && lane == 0) {
        float inflow = g_inflow[0][b] + p_bucket;
        float H0 = H_last[b];
        float bh = S_last[2 * b + 0];
        float a  = S_last[2 * b + 1];
        float h  = fmaxf((H0 + inflow) - bh, 0.0f);
        float q  = theta_last[b] * sqrt_approx(19.6f * h) * a;
        out[1 + NM * NB + b]      = (H0 - q) + inflow;
        out[1 + NM * NB + NB + b] = q;
    }

    // reset barrier state for the next graph replay: the LAST block to exit
    // zeroes the counters (all others have stopped reading them by then).
    __syncthreads();
    if (tid == 0) {
        __threadfence();
        unsigned v = atomicAdd(&g_exit, 1u);
        if (v == NBLK - 1) { g_ctr = 0u; g_exit = 0u; __threadfence(); }
    }
}

// ---------------------------------------------------------------------------
extern "C" void kernel_launch(void* const* d_in, const int* in_sizes, int n_in,
                              void* d_out, int out_size)
{
    const float* H0         = (const float*)d_in[0];
    const float* H_mid      = (const float*)d_in[1];
    const float* H_last     = (const float*)d_in[2];
    const float* S0         = (const float*)d_in[3];
    const float* S_mid      = (const float*)d_in[4];
    const float* S_last     = (const float*)d_in[5];
    const float* theta0     = (const float*)d_in[6];
    const float* theta_mid  = (const float*)d_in[7];
    const float* theta_last = (const float*)d_in[8];
    const float* precip     = (const float*)d_in[9];
    float* out = (float*)d_out;

    const int smem_bytes = (2 * WPB + 1) * 12288;   // 184320 B
    static int configured = 0;
    if (!configured) {
        cudaFuncSetAttribute(k_cascade, cudaFuncAttributeMaxDynamicSharedMemorySize, smem_bytes);
        configured = 1;
    }
    k_cascade<<<NBLK, NTHR, smem_bytes>>>(H0, H_mid, H_last, S0, S_mid, S_last,
                                          theta0, theta_mid, theta_last, precip, out);
}

// round 6
// speedup vs baseline: 1.0612x; 1.0612x over previous
#include <cuda_runtime.h>
#include <cuda_bf16.h>
#include <cstdint>
#include <cstddef>

#define NB   1024
#define NM   14
#define NBLK 148
#define WPB  7                 // warps (=buckets) per block
#define NTHR (WPB * 32)        // 224

// Inflow ping-pong buffers + barrier state. Self-resetting per launch:
//  - inflow slots zeroed at kernel start / consumer-zeroed per layer
//  - g_ctr/g_exit reset by the last-exiting block
__device__ float    g_inflow[2][NB];
__device__ unsigned g_ctr;
__device__ unsigned g_exit;

__device__ __forceinline__ float sqrt_approx(float x) {
    float y; asm("sqrt.approx.f32 %0, %1;" : "=f"(y) : "f"(x)); return y;
}
__device__ __forceinline__ unsigned ld_acq(const unsigned* p) {
    unsigned v; asm volatile("ld.acquire.gpu.global.u32 %0, [%1];" : "=r"(v) : "l"(p)); return v;
}

// ---- TMA bulk + mbarrier helpers -----------------------------------------
__device__ __forceinline__ void mbar_init(uint32_t a, uint32_t cnt) {
    asm volatile("mbarrier.init.shared.b64 [%0], %1;" :: "r"(a), "r"(cnt) : "memory");
}
__device__ __forceinline__ void mbar_expect(uint32_t a, uint32_t bytes) {
    asm volatile("mbarrier.arrive.expect_tx.shared.b64 _, [%0], %1;" :: "r"(a), "r"(bytes) : "memory");
}
__device__ __forceinline__ void mbar_wait(uint32_t a, uint32_t ph) {
    asm volatile(
        "{\n\t.reg .pred P;\n"
        "W%=:\n\t"
        "mbarrier.try_wait.parity.acquire.cta.shared::cta.b64 P, [%0], %1, 0x989680;\n\t"
        "@P bra D%=;\n\t"
        "bra W%=;\n"
        "D%=:\n\t}"
        :: "r"(a), "r"(ph) : "memory");
}
__device__ __forceinline__ void bulk_cp(uint32_t dst, const void* src, uint32_t bytes, uint32_t mbar) {
    asm volatile("cp.async.bulk.shared::cta.global.mbarrier::complete_tx::bytes [%0], [%1], %2, [%3];"
                 :: "r"(dst), "l"(src), "r"(bytes), "r"(mbar) : "memory");
}
__device__ __forceinline__ void fence_async() {
    asm volatile("fence.proxy.async.shared::cta;" ::: "memory");
}

// Grid barrier (all blocks resident). Monotonic counter, acquire-poll release.
__device__ __forceinline__ void grid_barrier(unsigned target) {
    __syncthreads();
    if (threadIdx.x == 0) {
        __threadfence();
        atomicAdd(&g_ctr, 1u);
        while (ld_acq(&g_ctr) < target) { }
    }
    __syncthreads();
}

// ---- per-lane min(bh) of window `lane` (XOR-staggered to tame conflicts) --
__device__ __forceinline__ float window_min(const char* bucket, int lane) {
    const float4* W4 = (const float4*)bucket;   // 512 float4 = (bh,a,bh,a)
    float m = 1e30f;
    #pragma unroll
    for (int i = 0; i < 16; ++i) {
        int j = (i + lane) & 15;
        float4 v = W4[lane * 16 + j];
        m = fminf(m, fminf(v.x, v.z));
    }
    return m;
}

// ---- exact sequential bucket recurrence with window skipping --------------
// Dry spigots: q==0 and H_eff bit-identical => skipped exactly. H_eff is
// monotone nonincreasing after spigot 0, so windows whose min bh >= H_eff
// never fire again. Windows processed in index order; within a window the
// lowest firing index goes first (ballot+ffs) => reference order preserved.
template <bool ATOMIC>
__device__ float chain_smem(const char* bucket, int lane, float minbh,
                            float H0, float inflow, float* __restrict__ nxt)
{
    const unsigned FULL = 0xFFFFFFFFu;
    const float SQ2G = 4.4271887242357310f;      // sqrt(2*9.8)
    const float2* __restrict__ S2 = (const float2*)bucket;
    const float*  __restrict__ T  = (const float*)(bucket + 8192);

    // spigot 0: H_eff = H0 + inflow (reference quirk)
    float2 s0 = S2[0];
    float  t0 = T[0];
    float  h0 = fmaxf((H0 + inflow) - s0.x, 0.0f);
    float  q0 = t0 * s0.y * SQ2G * sqrt_approx(h0);
    float  cum = q0;
    float  H_eff = fmaf(-0.5f, cum, H0);
    if (lane == 0 && q0 != 0.0f) {
        if (ATOMIC) atomicAdd(&nxt[0], q0); else nxt[0] = q0;
    }

    unsigned wrem = FULL;
    while (true) {
        unsigned wf = __ballot_sync(FULL, H_eff > minbh) & wrem;
        if (!wf) break;
        int w = __ffs(wf) - 1;                   // next window with a firing spigot
        wrem &= (0xFFFFFFFEu << w);              // windows <= w finished forever
        float2 p  = S2[w * 32 + lane];
        float  th = T [w * 32 + lane];
        float  bh = p.x;
        float  cc = p.y * th * SQ2G;
        float  qacc = 0.0f;
        unsigned rem = (w == 0) ? 0xFFFFFFFEu : FULL;   // spigot 0 already done
        while (true) {
            float h = H_eff - bh;
            unsigned fire = __ballot_sync(FULL, h > 0.0f) & rem;
            if (!fire) break;
            float q = cc * sqrt_approx(h);       // only firing lane's q consumed
            int f = __ffs(fire) - 1;
            float qf = __shfl_sync(FULL, q, f);
            cum += qf;
            H_eff = fmaf(-0.5f, cum, H0);
            qacc = (lane == f) ? qf : qacc;
            rem &= (0xFFFFFFFEu << f);
        }
        if (qacc != 0.0f) {
            if (ATOMIC) atomicAdd(&nxt[w * 32 + lane], qacc);
            else        nxt[w * 32 + lane] = qacc;
        }
    }
    return cum;
}

// ---------------------------------------------------------------------------
// Persistent kernel: 148 blocks x 224 threads, 1 block/SM.
// smem: buf[2][7][12288] | head[12288]; mbars in static shared.
// Layer l chains from buf[l&1] while TMA stages layer l+1 into buf[(l&1)^1].
// ---------------------------------------------------------------------------
__global__ void __launch_bounds__(NTHR, 1)
k_cascade(const float* __restrict__ H0p,   const float* __restrict__ H_mid,
          const float* __restrict__ H_last,const float* __restrict__ S0,
          const float* __restrict__ S_mid, const float* __restrict__ S_last,
          const float* __restrict__ theta0,const float* __restrict__ theta_mid,
          const float* __restrict__ theta_last, const float* __restrict__ precip,
          float* __restrict__ out)
{
    extern __shared__ char smem[];
    __shared__ uint64_t s_mbar[WPB * 2 + 1];     // [w*2+buf], head at [14]

    const int tid  = threadIdx.x;
    const int lane = tid & 31;
    const int w    = tid >> 5;                   // 0..6
    const int b    = blockIdx.x * WPB + w;       // bucket id (may be >= NB)

    char* mybuf[2] = { smem + w * 12288, smem + (WPB + w) * 12288 };
    char* headb    = smem + 2 * WPB * 12288;
    const uint32_t mb0 = (uint32_t)__cvta_generic_to_shared(&s_mbar[w * 2 + 0]);
    const uint32_t mb1 = (uint32_t)__cvta_generic_to_shared(&s_mbar[w * 2 + 1]);
    const uint32_t mbh = (uint32_t)__cvta_generic_to_shared(&s_mbar[WPB * 2]);
    const uint32_t sb0 = (uint32_t)__cvta_generic_to_shared(mybuf[0]);
    const uint32_t sb1 = (uint32_t)__cvta_generic_to_shared(mybuf[1]);
    const uint32_t sbh = (uint32_t)__cvta_generic_to_shared(headb);

    const float pre      = precip[0];
    const float p_layer  = pre * (1.0f / 16.0f);
    const float p_bucket = p_layer * (1.0f / 1024.0f);

    // init mbarriers, zero inflow slots
    if (lane == 0) { mbar_init(mb0, 1); mbar_init(mb1, 1); }
    if (tid == 0)  mbar_init(mbh, 1);
    if (lane == 0 && b < NB) { g_inflow[0][b] = 0.0f; g_inflow[1][b] = 0.0f; }
    fence_async();
    __syncthreads();

    // stage mid layer 0 (buf0) + head bucket
    if (lane == 0 && b < NB) {
        mbar_expect(mb0, 12288);
        bulk_cp(sb0,        (const char*)S_mid     + (size_t)b * 8192, 8192, mb0);
        bulk_cp(sb0 + 8192, (const char*)theta_mid + (size_t)b * 4096, 4096, mb0);
    }
    if (tid == 0) {
        mbar_expect(mbh, 12288);
        bulk_cp(sbh,        (const char*)S0,     8192, mbh);
        bulk_cp(sbh + 8192, (const char*)theta0, 4096, mbh);
    }

    unsigned phase = 1;
    grid_barrier(NBLK * phase); ++phase;         // inflow zeros visible

    // head bucket chain (block 0, warp 0) -> g_inflow[0] (plain stores)
    if (blockIdx.x == 0 && w == 0) {
        mbar_wait(mbh, 0);
        float mh = window_min(headb, lane);
        float H0 = H0p[0];
        float cum = chain_smem<false>(headb, lane, mh, H0, p_layer, g_inflow[0]);
        if (lane == 0) out[0] = (H0 - cum) + p_layer;
    }
    grid_barrier(NBLK * phase); ++phase;         // q0 visible

    int ph[2] = {0, 0};
    for (int l = 0; l < NM; ++l) {
        const int cur = l & 1;
        __syncwarp();
        // stage layer l+1 into the other buffer (previous use finished at l-1)
        if (l + 1 < NM && b < NB && lane == 0) {
            fence_async();
            uint32_t mbn = cur ? mb0 : mb1;
            uint32_t sbn = cur ? sb0 : sb1;
            size_t row = (size_t)(l + 1) * NB + (size_t)b;
            mbar_expect(mbn, 12288);
            bulk_cp(sbn,        (const char*)S_mid     + row * 8192, 8192, mbn);
            bulk_cp(sbn + 8192, (const char*)theta_mid + row * 4096, 4096, mbn);
        }

        if (b < NB) {
            // issue inflow/H0 loads early, overlap with mbar wait + minbh
            float inf0 = 0.0f;
            if (lane == 0) { inf0 = g_inflow[cur][b]; g_inflow[cur][b] = 0.0f; }
            float H0 = H_mid[(size_t)l * NB + b];
            mbar_wait(cur ? mb1 : mb0, ph[cur]); ph[cur] ^= 1;
            float mh = window_min(mybuf[cur], lane);
            float inflow = __shfl_sync(0xFFFFFFFFu, inf0, 0) + p_bucket;
            float cum = chain_smem<true>(mybuf[cur], lane, mh, H0, inflow,
                                         g_inflow[cur ^ 1]);
            if (lane == 0) out[1 + l * NB + b] = (H0 - cum) + inflow;
        }
        grid_barrier(NBLK * phase); ++phase;     // layer-l atomics visible
    }

    // last layer: one outlet spigot per bucket (inflows in g_inflow[0])
    if (b < NB && lane == 0) {
        float inflow = g_inflow[0][b] + p_bucket;
        float H0 = H_last[b];
        float bh = S_last[2 * b + 0];
        float a  = S_last[2 * b + 1];
        float h  = fmaxf((H0 + inflow) - bh, 0.0f);
        float q  = theta_last[b] * sqrt_approx(19.6f * h) * a;
        out[1 + NM * NB + b]      = (H0 - q) + inflow;
        out[1 + NM * NB + NB + b] = q;
    }

    // reset barrier state for the next graph replay (last block to exit)
    __syncthreads();
    if (tid == 0) {
        __threadfence();
        unsigned v = atomicAdd(&g_exit, 1u);
        if (v == NBLK - 1) { g_ctr = 0u; g_exit = 0u; __threadfence(); }
    }
}

// ---------------------------------------------------------------------------
extern "C" void kernel_launch(void* const* d_in, const int* in_sizes, int n_in,
                              void* d_out, int out_size)
{
    const float* H0         = (const float*)d_in[0];
    const float* H_mid      = (const float*)d_in[1];
    const float* H_last     = (const float*)d_in[2];
    const float* S0         = (const float*)d_in[3];
    const float* S_mid      = (const float*)d_in[4];
    const float* S_last     = (const float*)d_in[5];
    const float* theta0     = (const float*)d_in[6];
    const float* theta_mid  = (const float*)d_in[7];
    const float* theta_last = (const float*)d_in[8];
    const float* precip     = (const float*)d_in[9];
    float* out = (float*)d_out;

    const int smem_bytes = (2 * WPB + 1) * 12288;   // 184320 B
    cudaFuncSetAttribute(k_cascade, cudaFuncAttributeMaxDynamicSharedMemorySize, smem_bytes);
    k_cascade<<<NBLK, NTHR, smem_bytes>>>(H0, H_mid, H_last, S0, S_mid, S_last,
                                          theta0, theta_mid, theta_last, precip, out);
}

// round 7
// speedup vs baseline: 1.6521x; 1.5567x over previous
#include <cuda_runtime.h>
#include <cuda_bf16.h>
#include <cstdint>
#include <cstddef>

#define NB   1024
#define NM   14
#define NBLK 148
#define WPB  7                  // warps (=buckets) per block
#define NTHR (WPB * 32)         // 224
#define NTOT (NBLK * NTHR)      // 33152 threads
#define PF0  8                  // layers prefetched ahead (~100 MB in L2)

// Inflow ping-pong buffers + barrier state. Self-resetting per launch:
// zeros written at start / consumer-zeroed per layer; g_ctr/g_exit reset by
// the last-exiting block so graph replays start clean.
__device__ float    g_inflow[2][NB];
__device__ unsigned g_ctr;
__device__ unsigned g_exit;

__device__ __forceinline__ float sqrt_approx(float x) {
    float y; asm("sqrt.approx.f32 %0, %1;" : "=f"(y) : "f"(x)); return y;
}
__device__ __forceinline__ unsigned ld_acq(const unsigned* p) {
    unsigned v; asm volatile("ld.acquire.gpu.global.u32 %0, [%1];" : "=r"(v) : "l"(p)); return v;
}
__device__ __forceinline__ void l2pf(const void* p) {
    asm volatile("prefetch.global.L2 [%0];" :: "l"(p));
}

// Grid barrier: all 148 blocks resident (1 block/SM). Monotonic counter.
__device__ __forceinline__ void grid_barrier(unsigned target) {
    __syncthreads();
    if (threadIdx.x == 0) {
        __threadfence();
        atomicAdd(&g_ctr, 1u);
        while (ld_acq(&g_ctr) < target) { }
    }
    __syncthreads();
}

// Prefetch one mid layer's S (8 MB) + theta (4 MB) into L2; 3 lines/thread.
__device__ __forceinline__ void prefetch_layer(const char* Sb, const char* Tb,
                                               int l, int t) {
    const char* S = Sb + (size_t)l * 8388608;
    const char* T = Tb + (size_t)l * 4194304;
    #pragma unroll
    for (int k = 0; k < 3; ++k) {
        long line = (long)t + (long)k * NTOT;
        if (line < 65536)       l2pf(S + line * 128);
        else if (line < 98304)  l2pf(T + (line - 65536) * 128);
    }
}

// Stage a bucket row into registers: lane holds spigots {w*32+lane}.
__device__ __forceinline__ void stage_regs(const float2* __restrict__ S2,
                                           const float* __restrict__ T,
                                           int lane, float bh[32], float cc[32]) {
    const float SQ2G = 4.4271887242357310f;   // sqrt(2*9.8)
    #pragma unroll
    for (int w = 0; w < 32; ++w) {
        float2 p = S2[w * 32 + lane];
        bh[w] = p.x; cc[w] = p.y;
    }
    #pragma unroll
    for (int w = 0; w < 32; ++w)
        cc[w] = cc[w] * T[w * 32 + lane] * SQ2G;
}

// Exact sequential recurrence. Dry spigots give q==0 and leave H_eff
// bit-identical -> only firing spigots (lowest index first via ballot) are
// serialized. Windows drain in index order; reference order preserved.
template <bool ATOMIC>
__device__ float chain_regs(int lane, float H0, float inflow,
                            const float bh[32], const float cc[32],
                            float* __restrict__ nxt)
{
    const unsigned FULL = 0xFFFFFFFFu;
    // spigot 0: H_eff = H0 + inflow (reference quirk)
    float bh0 = __shfl_sync(FULL, bh[0], 0);
    float cc0 = __shfl_sync(FULL, cc[0], 0);
    float h0  = fmaxf((H0 + inflow) - bh0, 0.0f);
    float q0  = cc0 * sqrt_approx(h0);
    float cum = q0;
    float H_eff = fmaf(-0.5f, cum, H0);
    if (lane == 0 && q0 != 0.0f) {
        if (ATOMIC) atomicAdd(&nxt[0], q0); else nxt[0] = q0;
    }
    #pragma unroll
    for (int w = 0; w < 32; ++w) {
        float qacc = 0.0f;
        unsigned rem = (w == 0) ? 0xFFFFFFFEu : FULL;   // spigot 0 done
        while (true) {
            float h = H_eff - bh[w];
            unsigned fire = __ballot_sync(FULL, h > 0.0f) & rem;
            if (!fire) break;
            float q = cc[w] * sqrt_approx(h);           // speculative
            int f = __ffs(fire) - 1;                    // lowest firing spigot
            float qf = __shfl_sync(FULL, q, f);
            cum += qf;
            H_eff = fmaf(-0.5f, cum, H0);
            qacc = (lane == f) ? qf : qacc;
            rem &= (0xFFFFFFFEu << f);
        }
        if (qacc != 0.0f) {
            if (ATOMIC) atomicAdd(&nxt[w * 32 + lane], qacc);
            else        nxt[w * 32 + lane] = qacc;
        }
    }
    return cum;
}

// ---------------------------------------------------------------------------
// Persistent kernel: 148 blocks x 224 threads, 1 block/SM. No big smem —
// chains are register-resident; layer data streams DRAM->L2 far ahead via
// prefetch, staging loads are L2 hits hoisted before each grid barrier.
// ---------------------------------------------------------------------------
__global__ void __launch_bounds__(NTHR, 1)
k_cascade(const float* __restrict__ H0p,   const float* __restrict__ H_mid,
          const float* __restrict__ H_last,const float* __restrict__ S0,
          const float* __restrict__ S_mid, const float* __restrict__ S_last,
          const float* __restrict__ theta0,const float* __restrict__ theta_mid,
          const float* __restrict__ theta_last, const float* __restrict__ precip,
          float* __restrict__ out)
{
    const int tid  = threadIdx.x;
    const int lane = tid & 31;
    const int w    = tid >> 5;                    // 0..6
    const int b    = blockIdx.x * WPB + w;        // bucket id (may be >= NB)
    const int t    = blockIdx.x * NTHR + tid;     // linear thread id

    // issue the DRAM stream for layers 0..PF0-1 immediately (layer order)
    for (int l = 0; l < PF0 && l < NM; ++l)
        prefetch_layer((const char*)S_mid, (const char*)theta_mid, l, t);

    if (lane == 0 && b < NB) { g_inflow[0][b] = 0.0f; g_inflow[1][b] = 0.0f; }

    const float pre      = precip[0];
    const float p_layer  = pre * (1.0f / 16.0f);
    const float p_bucket = p_layer * (1.0f / 1024.0f);

    unsigned phase = 1;
    grid_barrier(NBLK * phase); ++phase;          // zeros visible

    float bh[32], cc[32];

    // head bucket (block 0 warp 0) -> plain stores into g_inflow[0]
    if (blockIdx.x == 0 && w == 0) {
        stage_regs((const float2*)S0, theta0, lane, bh, cc);
        float H0 = H0p[0];
        float cum = chain_regs<false>(lane, H0, p_layer, bh, cc, g_inflow[0]);
        if (lane == 0) out[0] = (H0 - cum) + p_layer;
    }
    // everyone stages layer 0 (overlaps the head chain)
    if (b < NB)
        stage_regs((const float2*)S_mid + (size_t)b * NB,
                   theta_mid + (size_t)b * NB, lane, bh, cc);

    grid_barrier(NBLK * phase); ++phase;          // q0 visible

    for (int l = 0; l < NM; ++l) {
        const int cur = l & 1;
        if (b < NB) {
            float inf0 = 0.0f;
            if (lane == 0) { inf0 = g_inflow[cur][b]; g_inflow[cur][b] = 0.0f; }
            float H0 = H_mid[(size_t)l * NB + b];
            float inflow = __shfl_sync(0xFFFFFFFFu, inf0, 0) + p_bucket;
            float cum = chain_regs<true>(lane, H0, inflow, bh, cc,
                                         g_inflow[cur ^ 1]);
            if (lane == 0) out[1 + l * NB + b] = (H0 - cum) + inflow;
        }
        // keep the DRAM stream rolling + stage l+1 BEFORE the barrier
        if (l + PF0 < NM)
            prefetch_layer((const char*)S_mid, (const char*)theta_mid, l + PF0, t);
        if (l + 1 < NM && b < NB) {
            size_t row = (size_t)(l + 1) * NB + (size_t)b;
            stage_regs((const float2*)S_mid + row * NB,
                       theta_mid + row * NB, lane, bh, cc);
        }
        grid_barrier(NBLK * phase); ++phase;      // layer-l atomics visible
    }

    // last layer: one outlet spigot per bucket (final inflows in g_inflow[0])
    if (b < NB && lane == 0) {
        float inflow = g_inflow[0][b] + p_bucket;
        float H0 = H_last[b];
        float sh = S_last[2 * b + 0];
        float a  = S_last[2 * b + 1];
        float h  = fmaxf((H0 + inflow) - sh, 0.0f);
        float q  = theta_last[b] * sqrt_approx(19.6f * h) * a;
        out[1 + NM * NB + b]      = (H0 - q) + inflow;
        out[1 + NM * NB + NB + b] = q;
    }

    // reset barrier state for the next graph replay (last block to exit)
    __syncthreads();
    if (tid == 0) {
        __threadfence();
        unsigned v = atomicAdd(&g_exit, 1u);
        if (v == NBLK - 1) { g_ctr = 0u; g_exit = 0u; __threadfence(); }
    }
}

// ---------------------------------------------------------------------------
extern "C" void kernel_launch(void* const* d_in, const int* in_sizes, int n_in,
                              void* d_out, int out_size)
{
    const float* H0         = (const float*)d_in[0];
    const float* H_mid      = (const float*)d_in[1];
    const float* H_last     = (const float*)d_in[2];
    const float* S0         = (const float*)d_in[3];
    const float* S_mid      = (const float*)d_in[4];
    const float* S_last     = (const float*)d_in[5];
    const float* theta0     = (const float*)d_in[6];
    const float* theta_mid  = (const float*)d_in[7];
    const float* theta_last = (const float*)d_in[8];
    const float* precip     = (const float*)d_in[9];
    float* out = (float*)d_out;

    k_cascade<<<NBLK, NTHR>>>(H0, H_mid, H_last, S0, S_mid, S_last,
                              theta0, theta_mid, theta_last, precip, out);
}